// round 1
// baseline (speedup 1.0000x reference)
#include <cuda_runtime.h>
#include <cuda_bf16.h>
#include <cstdint>

// Decoder (Conv-TasNet): out = overlap_add( (mixture_w * est_mask)^T @ W^T, step=L/2 )
// Shapes: mixture_w/est_mask [B, N, K] f32, W [L, N] f32, out [B, T] f32
// B=4, N=512, K=16000, L=16, step=8, T = 8*(K-1)+16 = 128008

#define DEC_B 4
#define DEC_N 512
#define DEC_K 16000
#define DEC_L 16
#define DEC_STEP 8
#define DEC_T (DEC_STEP * (DEC_K - 1) + DEC_L)   // 128008

#define TPB 128

__global__ __launch_bounds__(TPB)
void decoder_kernel(const float* __restrict__ mw,
                    const float* __restrict__ em,
                    const float* __restrict__ W,
                    float* __restrict__ out)
{
    // W is [L, N] row-major; stage transposed as Ws[n][l] so the inner loop
    // reads 16 consecutive floats per n via 4x LDS.128 (warp-broadcast).
    __shared__ float Ws[DEC_N * DEC_L];   // 32 KB
    for (int i = threadIdx.x; i < DEC_N * DEC_L; i += TPB) {
        int n = i >> 4;
        int l = i & 15;
        Ws[i] = W[l * DEC_N + n];
    }
    __syncthreads();

    const int b = blockIdx.y;
    const int k = blockIdx.x * TPB + threadIdx.x;
    if (k >= DEC_K) return;

    const float* __restrict__ mwp = mw + (size_t)b * DEC_N * DEC_K + k;
    const float* __restrict__ emp = em + (size_t)b * DEC_N * DEC_K + k;

    float acc[DEC_L];
#pragma unroll
    for (int l = 0; l < DEC_L; ++l) acc[l] = 0.0f;

#pragma unroll 4
    for (int n = 0; n < DEC_N; ++n) {
        // coalesced: lanes read consecutive k for fixed (b, n)
        float p = mwp[(size_t)n * DEC_K] * emp[(size_t)n * DEC_K];

        const float4* w4 = reinterpret_cast<const float4*>(&Ws[n * DEC_L]);
        float4 w0 = w4[0];
        float4 w1 = w4[1];
        float4 w2 = w4[2];
        float4 w3 = w4[3];

        acc[0]  = fmaf(p, w0.x, acc[0]);
        acc[1]  = fmaf(p, w0.y, acc[1]);
        acc[2]  = fmaf(p, w0.z, acc[2]);
        acc[3]  = fmaf(p, w0.w, acc[3]);
        acc[4]  = fmaf(p, w1.x, acc[4]);
        acc[5]  = fmaf(p, w1.y, acc[5]);
        acc[6]  = fmaf(p, w1.z, acc[6]);
        acc[7]  = fmaf(p, w1.w, acc[7]);
        acc[8]  = fmaf(p, w2.x, acc[8]);
        acc[9]  = fmaf(p, w2.y, acc[9]);
        acc[10] = fmaf(p, w2.z, acc[10]);
        acc[11] = fmaf(p, w2.w, acc[11]);
        acc[12] = fmaf(p, w3.x, acc[12]);
        acc[13] = fmaf(p, w3.y, acc[13]);
        acc[14] = fmaf(p, w3.z, acc[14]);
        acc[15] = fmaf(p, w3.w, acc[15]);
    }

    // Overlap-add: frame k covers out[b, 8k .. 8k+15]. Each output element
    // receives at most 2 contributions; 2-operand fp32 add is commutative,
    // so atomicAdd here is bit-deterministic.
    float* __restrict__ op = out + (size_t)b * DEC_T + (size_t)k * DEC_STEP;
#pragma unroll
    for (int l = 0; l < DEC_L; ++l) {
        atomicAdd(&op[l], acc[l]);
    }
}

extern "C" void kernel_launch(void* const* d_in, const int* in_sizes, int n_in,
                              void* d_out, int out_size)
{
    const float* mixture_w = (const float*)d_in[0];  // [B, N, K]
    const float* est_mask  = (const float*)d_in[1];  // [B, N, K]
    const float* W         = (const float*)d_in[2];  // [L, N]
    float* out = (float*)d_out;                       // [B, T]

    // Zero output (graph-capturable memset node), then accumulate.
    cudaMemsetAsync(out, 0, (size_t)out_size * sizeof(float), 0);

    dim3 grid((DEC_K + TPB - 1) / TPB, DEC_B);
    decoder_kernel<<<grid, TPB>>>(mixture_w, est_mask, W, out);
}

// round 2
// speedup vs baseline: 1.5067x; 1.5067x over previous
#include <cuda_runtime.h>
#include <cuda_bf16.h>
#include <cstdint>

// Decoder (Conv-TasNet): out = overlap_add( (mixture_w * est_mask)^T @ W^T, step=L/2 )
// mixture_w/est_mask [B, N, K] f32, W [L, N] f32, out [B, T] f32
// B=4, N=512, K=16000, L=16, step=8, T = 8*(K-1)+16 = 128008

#define DEC_B 4
#define DEC_N 512
#define DEC_K 16000
#define DEC_L 16
#define DEC_STEP 8
#define DEC_T (DEC_STEP * (DEC_K - 1) + DEC_L)   // 128008

#define TPB 128
#define NSPLIT 4
#define NCHUNK (DEC_N / NSPLIT)      // 128
#define KPT 2                         // frames per thread (float2 along k)
#define ACC_SPAN (DEC_STEP * KPT + DEC_STEP)  // 24 unique out positions per thread

__global__ __launch_bounds__(TPB)
void decoder_kernel(const float* __restrict__ mw,
                    const float* __restrict__ em,
                    const float* __restrict__ W,
                    float* __restrict__ out)
{
    // Stage this block's N-chunk of W transposed: Ws[n_local][l], 8 KB.
    __shared__ float Ws[NCHUNK * DEC_L];
    const int nb = blockIdx.z * NCHUNK;
    for (int i = threadIdx.x; i < NCHUNK * DEC_L; i += TPB) {
        int n = i >> 4;
        int l = i & 15;
        Ws[i] = W[l * DEC_N + nb + n];
    }
    __syncthreads();

    const int b  = blockIdx.y;
    const int k0 = (blockIdx.x * TPB + threadIdx.x) * KPT;
    if (k0 >= DEC_K) return;   // K even, so k0 valid => k0+1 valid

    const size_t base = (size_t)b * DEC_N * DEC_K + (size_t)nb * DEC_K + k0;
    const float2* __restrict__ mwp = reinterpret_cast<const float2*>(mw + base);
    const float2* __restrict__ emp = reinterpret_cast<const float2*>(em + base);

    // Frames k0 and k0+1 overlap by 8: acc[0..15] <- frame0, acc[8..23] <- frame1.
    float acc[ACC_SPAN];
#pragma unroll
    for (int i = 0; i < ACC_SPAN; ++i) acc[i] = 0.0f;

#pragma unroll 4
    for (int n = 0; n < NCHUNK; ++n) {
        // coalesced + streaming (each input byte read exactly once chip-wide)
        float2 m = __ldcs(&mwp[(size_t)n * (DEC_K / 2)]);
        float2 e = __ldcs(&emp[(size_t)n * (DEC_K / 2)]);
        float p0 = m.x * e.x;
        float p1 = m.y * e.y;

        const float4* w4 = reinterpret_cast<const float4*>(&Ws[n * DEC_L]);
        float4 w0 = w4[0];
        float4 w1 = w4[1];
        float4 w2 = w4[2];
        float4 w3 = w4[3];

        acc[0]  = fmaf(p0, w0.x, acc[0]);
        acc[1]  = fmaf(p0, w0.y, acc[1]);
        acc[2]  = fmaf(p0, w0.z, acc[2]);
        acc[3]  = fmaf(p0, w0.w, acc[3]);
        acc[4]  = fmaf(p0, w1.x, acc[4]);
        acc[5]  = fmaf(p0, w1.y, acc[5]);
        acc[6]  = fmaf(p0, w1.z, acc[6]);
        acc[7]  = fmaf(p0, w1.w, acc[7]);
        acc[8]  = fmaf(p0, w2.x, acc[8]);
        acc[9]  = fmaf(p0, w2.y, acc[9]);
        acc[10] = fmaf(p0, w2.z, acc[10]);
        acc[11] = fmaf(p0, w2.w, acc[11]);
        acc[12] = fmaf(p0, w3.x, acc[12]);
        acc[13] = fmaf(p0, w3.y, acc[13]);
        acc[14] = fmaf(p0, w3.z, acc[14]);
        acc[15] = fmaf(p0, w3.w, acc[15]);

        acc[8]  = fmaf(p1, w0.x, acc[8]);
        acc[9]  = fmaf(p1, w0.y, acc[9]);
        acc[10] = fmaf(p1, w0.z, acc[10]);
        acc[11] = fmaf(p1, w0.w, acc[11]);
        acc[12] = fmaf(p1, w1.x, acc[12]);
        acc[13] = fmaf(p1, w1.y, acc[13]);
        acc[14] = fmaf(p1, w1.z, acc[14]);
        acc[15] = fmaf(p1, w1.w, acc[15]);
        acc[16] = fmaf(p1, w2.x, acc[16]);
        acc[17] = fmaf(p1, w2.y, acc[17]);
        acc[18] = fmaf(p1, w2.z, acc[18]);
        acc[19] = fmaf(p1, w2.w, acc[19]);
        acc[20] = fmaf(p1, w3.x, acc[20]);
        acc[21] = fmaf(p1, w3.y, acc[21]);
        acc[22] = fmaf(p1, w3.z, acc[22]);
        acc[23] = fmaf(p1, w3.w, acc[23]);
    }

    // Scatter-add the 24 unique positions covered by frames k0, k0+1.
    // Each out element receives <= 2*NSPLIT = 8 fp32 contributions (atomic).
    float* __restrict__ op = out + (size_t)b * DEC_T + (size_t)k0 * DEC_STEP;
#pragma unroll
    for (int i = 0; i < ACC_SPAN; ++i) {
        atomicAdd(&op[i], acc[i]);
    }
}

extern "C" void kernel_launch(void* const* d_in, const int* in_sizes, int n_in,
                              void* d_out, int out_size)
{
    const float* mixture_w = (const float*)d_in[0];  // [B, N, K]
    const float* est_mask  = (const float*)d_in[1];  // [B, N, K]
    const float* W         = (const float*)d_in[2];  // [L, N]
    float* out = (float*)d_out;                       // [B, T]

    cudaMemsetAsync(out, 0, (size_t)out_size * sizeof(float), 0);

    dim3 grid((DEC_K + TPB * KPT - 1) / (TPB * KPT), DEC_B, NSPLIT);  // (63, 4, 4)
    decoder_kernel<<<grid, TPB>>>(mixture_w, est_mask, W, out);
}